// round 1
// baseline (speedup 1.0000x reference)
#include <cuda_runtime.h>
#include <math.h>

#define T_SEQ 2048
#define BATCH 256
#define KS 112  // k-range of Whh kept in smem; tail 16 k's live in registers

// xg scratch: [B][T][4H] fp32 = 1 GiB. __device__ global (no cudaMalloc allowed).
__device__ float g_xg[268435456];

__device__ __forceinline__ float sigf(float x) {
    return __fdividef(1.f, 1.f + __expf(-x));
}
// overflow-safe tanh: exp argument always <= 0
__device__ __forceinline__ float tanhx(float x) {
    float a = fabsf(x);
    float e = __expf(-2.f * a);
    float r = __fdividef(1.f - e, 1.f + e);
    return copysignf(r, x);
}

// ---------------------------------------------------------------------------
// Kernel A: xg[b,t,g] = sum_d x[b,t,d] * Wih[g,d] + bih[g] + bhh[g]
// M = B*T = 524288 (rows), K = 128, N = 512 (split into 4 chunks of 128).
// Tile: 64 rows x 128 cols, 256 threads, each thread 8x4 outputs.
// B tile stored transposed [k][g] with XOR swizzle for conflict-free LDS.128.
// ---------------------------------------------------------------------------
__global__ void __launch_bounds__(256, 2)
xg_gemm(const float* __restrict__ x, const float* __restrict__ Wih,
        const float* __restrict__ bih, const float* __restrict__ bhh)
{
    extern __shared__ float sm[];
    float* As = sm;           // [64][128] row-major, 32 KB
    float* Bs = sm + 8192;    // [128][128] transposed+swizzled, 64 KB

    const int tid = threadIdx.x;
    const int tx = tid & 31;      // col group (4 cols each)
    const int ty = tid >> 5;      // row group (8 rows each)
    const long row0 = (long)blockIdx.x * 64;
    const int g0 = blockIdx.y * 128;

    // Load A tile (contiguous copy, coalesced)
    {
        const float4* x4 = (const float4*)x + row0 * 32;
        float4* As4 = (float4*)As;
#pragma unroll
        for (int i = 0; i < 8; ++i) As4[i * 256 + tid] = x4[i * 256 + tid];
    }
    // Load B tile: Wih rows g0..g0+127, transpose to [k][g] with swizzle.
    // phys float idx = k*128 + 4*((g>>2) ^ (k&31)) + (g&3)
    {
        const float4* w4 = (const float4*)Wih + (long)g0 * 32;
#pragma unroll
        for (int i = 0; i < 16; ++i) {
            int idx = i * 256 + tid;          // 0..4095
            int gl = idx >> 5, k4 = idx & 31; // warp-coalesced global read
            float4 w = w4[gl * 32 + k4];
            int k = k4 * 4;
            Bs[(k + 0) * 128 + 4 * ((gl >> 2) ^ ((k + 0) & 31)) + (gl & 3)] = w.x;
            Bs[(k + 1) * 128 + 4 * ((gl >> 2) ^ ((k + 1) & 31)) + (gl & 3)] = w.y;
            Bs[(k + 2) * 128 + 4 * ((gl >> 2) ^ ((k + 2) & 31)) + (gl & 3)] = w.z;
            Bs[(k + 3) * 128 + 4 * ((gl >> 2) ^ ((k + 3) & 31)) + (gl & 3)] = w.w;
        }
    }
    __syncthreads();

    float4 acc[8];
#pragma unroll
    for (int i = 0; i < 8; ++i) acc[i] = make_float4(0.f, 0.f, 0.f, 0.f);

    const float4* As4 = (const float4*)As;
    const float4* Bs4 = (const float4*)Bs;

#pragma unroll 2
    for (int k4 = 0; k4 < 32; ++k4) {
        float4 a[8];
#pragma unroll
        for (int i = 0; i < 8; ++i) a[i] = As4[(ty * 8 + i) * 32 + k4];  // broadcast
#pragma unroll
        for (int kk = 0; kk < 4; ++kk) {
            int k = k4 * 4 + kk;
            float4 b = Bs4[k * 32 + (tx ^ (k & 31))];  // conflict-free via swizzle
#pragma unroll
            for (int i = 0; i < 8; ++i) {
                float av = (kk == 0) ? a[i].x : (kk == 1) ? a[i].y
                          : (kk == 2) ? a[i].z : a[i].w;
                acc[i].x += av * b.x; acc[i].y += av * b.y;
                acc[i].z += av * b.z; acc[i].w += av * b.w;
            }
        }
    }

    float4 bb;
    {
        float4 u = ((const float4*)bih)[(g0 >> 2) + tx];
        float4 v = ((const float4*)bhh)[(g0 >> 2) + tx];
        bb = make_float4(u.x + v.x, u.y + v.y, u.z + v.z, u.w + v.w);
    }

    float4* out4 = (float4*)g_xg;
#pragma unroll
    for (int i = 0; i < 8; ++i) {
        float4 r = acc[i];
        r.x += bb.x; r.y += bb.y; r.z += bb.z; r.w += bb.w;
        out4[(row0 + ty * 8 + i) * 128 + (g0 >> 2) + tx] = r;
    }
}

// ---------------------------------------------------------------------------
// Kernel B: LSTM recurrence. 128 CTAs x 2 batch rows, 128 threads/CTA.
// Thread t owns hidden index j=t: all 4 gates x 2 rows (8 accumulators).
// Whh[k<112] in smem transposed [k][512] (conflict-free scalar LDS),
// Whh[k>=112] in registers. h in smem (broadcast float4 loads). c in regs.
// Includes final output projection out = h_last @ Wo^T + bo.
// ---------------------------------------------------------------------------

#define STEPK(WPTR, HX0, HX1) { \
    float wi_ = (WPTR)[0], wf_ = (WPTR)[128], wg_ = (WPTR)[256], wo_ = (WPTR)[384]; \
    ai0 += wi_ * (HX0); ai1 += wi_ * (HX1); \
    af0 += wf_ * (HX0); af1 += wf_ * (HX1); \
    ag0 += wg_ * (HX0); ag1 += wg_ * (HX1); \
    ao0 += wo_ * (HX0); ao1 += wo_ * (HX1); }

#define STEPT(WI, WF, WG, WO, HX0, HX1) { \
    ai0 += (WI) * (HX0); ai1 += (WI) * (HX1); \
    af0 += (WF) * (HX0); af1 += (WF) * (HX1); \
    ag0 += (WG) * (HX0); ag1 += (WG) * (HX1); \
    ao0 += (WO) * (HX0); ao1 += (WO) * (HX1); }

__global__ void __launch_bounds__(128, 1)
lstm_rec(const float* __restrict__ Whh, const float* __restrict__ Wo,
         const float* __restrict__ bo, float* __restrict__ out)
{
    extern __shared__ float sm[];
    float* WT  = sm;               // [112][512] = 224 KB
    float* h0s = sm + KS * 512;    // [128]
    float* h1s = h0s + 128;        // [128]

    const int t = threadIdx.x;          // 0..127 = hidden index j
    const int lane = t & 31, wid = t >> 5;
    const int b0 = blockIdx.x * 2;

    // Load Whh transposed into smem for k in [0,112). Coalesced LDG.
    for (int gb = 0; gb < 512; gb += 4) {
        int g = gb + wid;
        const float* wr = Whh + g * 128;
        for (int kc = lane; kc < KS; kc += 32)
            WT[kc * 512 + g] = wr[kc];
    }
    // Tail weights k=112..127, 4 gate rows per thread -> 64 registers.
    float wt0[16], wt1[16], wt2[16], wt3[16];
#pragma unroll
    for (int q = 0; q < 4; ++q) {
        float4 v0 = *(const float4*)&Whh[(0 * 128 + t) * 128 + KS + 4 * q];
        float4 v1 = *(const float4*)&Whh[(1 * 128 + t) * 128 + KS + 4 * q];
        float4 v2 = *(const float4*)&Whh[(2 * 128 + t) * 128 + KS + 4 * q];
        float4 v3 = *(const float4*)&Whh[(3 * 128 + t) * 128 + KS + 4 * q];
        wt0[4*q+0] = v0.x; wt0[4*q+1] = v0.y; wt0[4*q+2] = v0.z; wt0[4*q+3] = v0.w;
        wt1[4*q+0] = v1.x; wt1[4*q+1] = v1.y; wt1[4*q+2] = v1.z; wt1[4*q+3] = v1.w;
        wt2[4*q+0] = v2.x; wt2[4*q+1] = v2.y; wt2[4*q+2] = v2.z; wt2[4*q+3] = v2.w;
        wt3[4*q+0] = v3.x; wt3[4*q+1] = v3.y; wt3[4*q+2] = v3.z; wt3[4*q+3] = v3.w;
    }

    h0s[t] = 0.f; h1s[t] = 0.f;
    float c0 = 0.f, c1 = 0.f;

    const float* xg0 = g_xg + (long)b0 * T_SEQ * 512;
    const float* xg1 = xg0 + (long)T_SEQ * 512;

    // Prefetch step 0 gate inputs
    float p00 = __ldg(xg0 + t),       p10 = __ldg(xg0 + 128 + t),
          p20 = __ldg(xg0 + 256 + t), p30 = __ldg(xg0 + 384 + t);
    float p01 = __ldg(xg1 + t),       p11 = __ldg(xg1 + 128 + t),
          p21 = __ldg(xg1 + 256 + t), p31 = __ldg(xg1 + 384 + t);

    __syncthreads();

    for (int step = 0; step < T_SEQ; ++step) {
        float ai0 = p00, af0 = p10, ag0 = p20, ao0 = p30;
        float ai1 = p01, af1 = p11, ag1 = p21, ao1 = p31;
        {   // prefetch next step's xg (latency fully hidden by FMA loop)
            int ns = (step + 1 < T_SEQ) ? step + 1 : step;
            const float* q0 = xg0 + (long)ns * 512 + t;
            const float* q1 = xg1 + (long)ns * 512 + t;
            p00 = __ldg(q0); p10 = __ldg(q0 + 128); p20 = __ldg(q0 + 256); p30 = __ldg(q0 + 384);
            p01 = __ldg(q1); p11 = __ldg(q1 + 128); p21 = __ldg(q1 + 256); p31 = __ldg(q1 + 384);
        }

        const float4* h04 = (const float4*)h0s;
        const float4* h14 = (const float4*)h1s;
#pragma unroll 2
        for (int k4 = 0; k4 < KS / 4; ++k4) {
            float4 H0 = h04[k4], H1 = h14[k4];
            const float* w = WT + (k4 * 4) * 512 + t;
            STEPK(w,        H0.x, H1.x)
            STEPK(w + 512,  H0.y, H1.y)
            STEPK(w + 1024, H0.z, H1.z)
            STEPK(w + 1536, H0.w, H1.w)
        }
        // register-held tail k = 112..127
#pragma unroll
        for (int q = 0; q < 4; ++q) {
            float4 H0 = h04[KS / 4 + q], H1 = h14[KS / 4 + q];
            STEPT(wt0[4*q+0], wt1[4*q+0], wt2[4*q+0], wt3[4*q+0], H0.x, H1.x)
            STEPT(wt0[4*q+1], wt1[4*q+1], wt2[4*q+1], wt3[4*q+1], H0.y, H1.y)
            STEPT(wt0[4*q+2], wt1[4*q+2], wt2[4*q+2], wt3[4*q+2], H0.z, H1.z)
            STEPT(wt0[4*q+3], wt1[4*q+3], wt2[4*q+3], wt3[4*q+3], H0.w, H1.w)
        }

        float i0 = sigf(ai0), f0 = sigf(af0), g0v = tanhx(ag0), o0 = sigf(ao0);
        float i1 = sigf(ai1), f1 = sigf(af1), g1v = tanhx(ag1), o1 = sigf(ao1);
        c0 = f0 * c0 + i0 * g0v;
        c1 = f1 * c1 + i1 * g1v;
        float nh0 = o0 * tanhx(c0);
        float nh1 = o1 * tanhx(c1);

        __syncthreads();              // all h reads for this step done
        h0s[t] = nh0; h1s[t] = nh1;
        __syncthreads();              // new h visible
    }

    // Output projection: out[b, o] = h_last[b,:] . Wo[o,:] + bo[o]
    float acc0 = bo[t], acc1 = acc0;
    const float4* wo4 = (const float4*)(Wo + t * 128);
    const float4* h04 = (const float4*)h0s;
    const float4* h14 = (const float4*)h1s;
#pragma unroll
    for (int k4 = 0; k4 < 32; ++k4) {
        float4 w = wo4[k4];
        float4 a = h04[k4];
        float4 b = h14[k4];
        acc0 += w.x * a.x + w.y * a.y + w.z * a.z + w.w * a.w;
        acc1 += w.x * b.x + w.y * b.y + w.z * b.z + w.w * b.w;
    }
    out[b0 * 128 + t] = acc0;
    out[(b0 + 1) * 128 + t] = acc1;
}

// ---------------------------------------------------------------------------

extern "C" void kernel_launch(void* const* d_in, const int* in_sizes, int n_in,
                              void* d_out, int out_size)
{
    const float* x   = (const float*)d_in[0];
    const float* Wih = (const float*)d_in[1];
    const float* Whh = (const float*)d_in[2];
    const float* bih = (const float*)d_in[3];
    const float* bhh = (const float*)d_in[4];
    const float* Wo  = (const float*)d_in[5];
    const float* bo  = (const float*)d_in[6];
    float* out = (float*)d_out;

    cudaFuncSetAttribute(xg_gemm, cudaFuncAttributeMaxDynamicSharedMemorySize, 98304);
    cudaFuncSetAttribute(lstm_rec, cudaFuncAttributeMaxDynamicSharedMemorySize, 230400);

    // Phase 1: xg = x @ Wih^T + bih + bhh   (grid: 8192 row-tiles x 4 col-chunks)
    xg_gemm<<<dim3(8192, 4), 256, 98304>>>(x, Wih, bih, bhh);
    // Phase 2: recurrence + output projection (128 independent CTAs, 2 rows each)
    lstm_rec<<<128, 128, 230400>>>(Whh, Wo, bo, out);
}

// round 2
// speedup vs baseline: 1.3600x; 1.3600x over previous
#include <cuda_runtime.h>
#include <math.h>

#define T_SEQ 2048
#define BATCH 256
#define KS 96          // k-range of Whh in smem; remaining 32 k in registers
#define WROW 258       // floats per k-row of WIF/WGO: 129 float2 pairs (pad vs 128)

typedef unsigned long long u64;

// xg scratch: [B][T][4H] fp32 = 1 GiB. __device__ global (no cudaMalloc allowed).
__device__ float g_xg[268435456];

// ---- f32x2 packed-math helpers (sm_103a FFMA2) --------------------------
__device__ __forceinline__ u64 pack2(float lo, float hi) {
    u64 r; asm("mov.b64 %0, {%1, %2};" : "=l"(r) : "f"(lo), "f"(hi)); return r;
}
__device__ __forceinline__ u64 dup2(float v) {
    u64 r; asm("mov.b64 %0, {%1, %1};" : "=l"(r) : "f"(v)); return r;
}
__device__ __forceinline__ void ffma2(u64& d, u64 a, u64 b) {
    asm("fma.rn.f32x2 %0, %1, %2, %0;" : "+l"(d) : "l"(a), "l"(b));
}
__device__ __forceinline__ void unpack2(u64 v, float& lo, float& hi) {
    asm("mov.b64 {%0, %1}, %2;" : "=f"(lo), "=f"(hi) : "l"(v));
}

__device__ __forceinline__ float sigf(float x) {
    return __fdividef(1.f, 1.f + __expf(-x));
}
// overflow-safe tanh: exp argument always <= 0
__device__ __forceinline__ float tanhx(float x) {
    float a = fabsf(x);
    float e = __expf(-2.f * a);
    float r = __fdividef(1.f - e, 1.f + e);
    return copysignf(r, x);
}

// ---------------------------------------------------------------------------
// Kernel A: xg[b,t,g] = sum_d x[b,t,d] * Wih[g,d] + bih[g] + bhh[g]
// Tile 64 rows x 128 cols, 256 threads. Accumulate COLUMN PAIRS with FFMA2:
// b operand = (W[g,k], W[g+1,k]) is a natural f32x2 in smem (ld.shared.b64,
// 2-way conflict = optimal), a operand = dup(x[row,k]) via mov.b64.
// B tile stored as two [128k][64] halves (cols 0..63 / 64..127 of the chunk).
// ---------------------------------------------------------------------------
__global__ void __launch_bounds__(256, 2)
xg_gemm(const float* __restrict__ x, const float* __restrict__ Wih,
        const float* __restrict__ bih, const float* __restrict__ bhh)
{
    extern __shared__ float sm[];
    float* As = sm;            // [64][128] row-major, 32 KB
    float* B0 = sm + 8192;     // [128][64] floats: cols g0+0..63
    float* B1 = B0 + 8192;     // [128][64] floats: cols g0+64..127

    const int tid = threadIdx.x;
    const int tx = tid & 31;      // owns col pair (2tx,2tx+1) in each half
    const int ty = tid >> 5;      // row group (8 rows)
    const long row0 = (long)blockIdx.x * 64;
    const int g0 = blockIdx.y * 128;

    // Load A tile (contiguous, coalesced)
    {
        const float4* x4 = (const float4*)x + row0 * 32;
        float4* As4 = (float4*)As;
#pragma unroll
        for (int i = 0; i < 8; ++i) As4[i * 256 + tid] = x4[i * 256 + tid];
    }
    // Load B: transpose Wih[g][k] -> half[k][g&63]. Lanes take consecutive g
    // (conflict-free STS); global reads are 16B/lane strided (L2-served, Wih hot).
    {
        const float4* w4 = (const float4*)Wih + (long)g0 * 32;
#pragma unroll
        for (int i = 0; i < 16; ++i) {
            int idx = i * 256 + tid;
            int q  = idx >> 7;     // k4: 0..31
            int gl = idx & 127;    // g-local, consecutive per lane
            float4 w = w4[(long)gl * 32 + q];
            float* dst = (gl < 64 ? B0 : B1) + (gl & 63);
            int k = q * 4;
            dst[(k + 0) * 64] = w.x;
            dst[(k + 1) * 64] = w.y;
            dst[(k + 2) * 64] = w.z;
            dst[(k + 3) * 64] = w.w;
        }
    }
    __syncthreads();

    u64 acc0[8], acc1[8];   // per row: pair in half0, pair in half1
#pragma unroll
    for (int i = 0; i < 8; ++i) { acc0[i] = 0ull; acc1[i] = 0ull; }

    const float4* As4 = (const float4*)As;

#pragma unroll 2
    for (int k4 = 0; k4 < 32; ++k4) {
        float4 a[8];
#pragma unroll
        for (int i = 0; i < 8; ++i) a[i] = As4[(ty * 8 + i) * 32 + k4];  // broadcast
#pragma unroll
        for (int c = 0; c < 4; ++c) {
            int k = 4 * k4 + c;
            u64 b0 = *(const u64*)(B0 + k * 64 + 2 * tx);
            u64 b1 = *(const u64*)(B1 + k * 64 + 2 * tx);
#pragma unroll
            for (int i = 0; i < 8; ++i) {
                float av = (c == 0) ? a[i].x : (c == 1) ? a[i].y
                          : (c == 2) ? a[i].z : a[i].w;
                u64 ad = dup2(av);
                ffma2(acc0[i], ad, b0);
                ffma2(acc1[i], ad, b1);
            }
        }
    }

    // bias pairs
    int c00 = g0 + 2 * tx, c10 = g0 + 64 + 2 * tx;
    float2 bv0 = make_float2(bih[c00] + bhh[c00], bih[c00 + 1] + bhh[c00 + 1]);
    float2 bv1 = make_float2(bih[c10] + bhh[c10], bih[c10 + 1] + bhh[c10 + 1]);

#pragma unroll
    for (int i = 0; i < 8; ++i) {
        long r = row0 + ty * 8 + i;
        float lo, hi;
        unpack2(acc0[i], lo, hi);
        *(float2*)&g_xg[r * 512 + c00] = make_float2(lo + bv0.x, hi + bv0.y);
        unpack2(acc1[i], lo, hi);
        *(float2*)&g_xg[r * 512 + c10] = make_float2(lo + bv1.x, hi + bv1.y);
    }
}

// ---------------------------------------------------------------------------
// Kernel B: LSTM recurrence. 128 CTAs x 2 batch rows, 128 threads/CTA.
// Thread t owns hidden j=t. Gate-pair FFMA2: accs (ai,af),(ag,ao) per row.
// Weights as interleaved float2 (wi,wf)/(wg,wo): WIF/WGO [KS][129 pairs] in
// smem (padded row=258 floats for transpose-store conflicts), tail 32 k in
// registers (128 regs). b operand = dup(h_row[k]) via mov.b64 (ALU pipe).
// ---------------------------------------------------------------------------
__global__ void __launch_bounds__(128, 1)
lstm_rec(const float* __restrict__ Whh, const float* __restrict__ Wo,
         const float* __restrict__ bo, float* __restrict__ out)
{
    extern __shared__ float sm[];
    float* WIF = sm;                     // [KS][WROW] floats
    float* WGO = sm + KS * WROW;         // [KS][WROW]
    float* h0s = WGO + KS * WROW;        // [128]
    float* h1s = h0s + 128;              // [128]

    const int t = threadIdx.x;
    const int lane = t & 31, w = t >> 5;
    const int b0 = blockIdx.x * 2;

    // Fill smem weights: warp w takes j = jj + w; lanes take k4 (coalesced LDG).
    for (int jj = 0; jj < 128; jj += 4) {
        int j = jj + w;
        if (lane < KS / 4) {
            int k4 = lane;
            float4 vi = *(const float4*)&Whh[(0 * 128 + j) * 128 + 4 * k4];
            float4 vf = *(const float4*)&Whh[(1 * 128 + j) * 128 + 4 * k4];
            float4 vg = *(const float4*)&Whh[(2 * 128 + j) * 128 + 4 * k4];
            float4 vo = *(const float4*)&Whh[(3 * 128 + j) * 128 + 4 * k4];
            int base = 4 * k4 * WROW + 2 * j;
            *(float2*)&WIF[base + 0 * WROW] = make_float2(vi.x, vf.x);
            *(float2*)&WIF[base + 1 * WROW] = make_float2(vi.y, vf.y);
            *(float2*)&WIF[base + 2 * WROW] = make_float2(vi.z, vf.z);
            *(float2*)&WIF[base + 3 * WROW] = make_float2(vi.w, vf.w);
            *(float2*)&WGO[base + 0 * WROW] = make_float2(vg.x, vo.x);
            *(float2*)&WGO[base + 1 * WROW] = make_float2(vg.y, vo.y);
            *(float2*)&WGO[base + 2 * WROW] = make_float2(vg.z, vo.z);
            *(float2*)&WGO[base + 3 * WROW] = make_float2(vg.w, vo.w);
        }
    }
    // Register tail: k = KS..127 as packed gate-pairs (64 u64 = 128 regs).
    u64 wifr[32], wgor[32];
#pragma unroll
    for (int q = 0; q < 32; ++q) {
        int k = KS + q;
        wifr[q] = pack2(Whh[(0 * 128 + t) * 128 + k], Whh[(1 * 128 + t) * 128 + k]);
        wgor[q] = pack2(Whh[(2 * 128 + t) * 128 + k], Whh[(3 * 128 + t) * 128 + k]);
    }

    h0s[t] = 0.f; h1s[t] = 0.f;
    float c0 = 0.f, c1 = 0.f;

    const float* xg0 = g_xg + (long)b0 * T_SEQ * 512;
    const float* xg1 = xg0 + (long)T_SEQ * 512;

    float p00 = __ldg(xg0 + t),       p10 = __ldg(xg0 + 128 + t),
          p20 = __ldg(xg0 + 256 + t), p30 = __ldg(xg0 + 384 + t);
    float p01 = __ldg(xg1 + t),       p11 = __ldg(xg1 + 128 + t),
          p21 = __ldg(xg1 + 256 + t), p31 = __ldg(xg1 + 384 + t);

    __syncthreads();

    for (int step = 0; step < T_SEQ; ++step) {
        u64 aif0 = pack2(p00, p10), ago0 = pack2(p20, p30);
        u64 aif1 = pack2(p01, p11), ago1 = pack2(p21, p31);
        {   // prefetch next step's xg
            int ns = (step + 1 < T_SEQ) ? step + 1 : step;
            const float* q0 = xg0 + (long)ns * 512 + t;
            const float* q1 = xg1 + (long)ns * 512 + t;
            p00 = __ldg(q0); p10 = __ldg(q0 + 128); p20 = __ldg(q0 + 256); p30 = __ldg(q0 + 384);
            p01 = __ldg(q1); p11 = __ldg(q1 + 128); p21 = __ldg(q1 + 256); p31 = __ldg(q1 + 384);
        }

        const float4* h04 = (const float4*)h0s;
        const float4* h14 = (const float4*)h1s;

#pragma unroll 6
        for (int k4 = 0; k4 < KS / 4; ++k4) {
            float4 H0 = h04[k4], H1 = h14[k4];
            const float* pif = WIF + (k4 * 4) * WROW + 2 * t;
            const float* pgo = WGO + (k4 * 4) * WROW + 2 * t;
#pragma unroll
            for (int c = 0; c < 4; ++c) {
                u64 wif = *(const u64*)(pif + c * WROW);
                u64 wgo = *(const u64*)(pgo + c * WROW);
                float hx0 = (c == 0) ? H0.x : (c == 1) ? H0.y : (c == 2) ? H0.z : H0.w;
                float hx1 = (c == 0) ? H1.x : (c == 1) ? H1.y : (c == 2) ? H1.z : H1.w;
                u64 h0d = dup2(hx0), h1d = dup2(hx1);
                ffma2(aif0, wif, h0d);
                ffma2(ago0, wgo, h0d);
                ffma2(aif1, wif, h1d);
                ffma2(ago1, wgo, h1d);
            }
        }
        // register-held tail k = KS..127
#pragma unroll
        for (int q = 0; q < 8; ++q) {
            float4 H0 = h04[KS / 4 + q], H1 = h14[KS / 4 + q];
#pragma unroll
            for (int c = 0; c < 4; ++c) {
                float hx0 = (c == 0) ? H0.x : (c == 1) ? H0.y : (c == 2) ? H0.z : H0.w;
                float hx1 = (c == 0) ? H1.x : (c == 1) ? H1.y : (c == 2) ? H1.z : H1.w;
                u64 h0d = dup2(hx0), h1d = dup2(hx1);
                ffma2(aif0, wifr[4 * q + c], h0d);
                ffma2(ago0, wgor[4 * q + c], h0d);
                ffma2(aif1, wifr[4 * q + c], h1d);
                ffma2(ago1, wgor[4 * q + c], h1d);
            }
        }

        float ai0, af0, ag0, ao0, ai1, af1, ag1, ao1;
        unpack2(aif0, ai0, af0); unpack2(ago0, ag0, ao0);
        unpack2(aif1, ai1, af1); unpack2(ago1, ag1, ao1);

        float i0 = sigf(ai0), f0 = sigf(af0), g0v = tanhx(ag0), o0 = sigf(ao0);
        float i1 = sigf(ai1), f1 = sigf(af1), g1v = tanhx(ag1), o1 = sigf(ao1);
        c0 = f0 * c0 + i0 * g0v;
        c1 = f1 * c1 + i1 * g1v;
        float nh0 = o0 * tanhx(c0);
        float nh1 = o1 * tanhx(c1);

        __syncthreads();              // all h reads for this step done
        h0s[t] = nh0; h1s[t] = nh1;
        __syncthreads();              // new h visible
    }

    // Output projection: out[b, o] = h_last[b,:] . Wo[o,:] + bo[o]
    float acc0 = bo[t], acc1 = acc0;
    const float4* wo4 = (const float4*)(Wo + t * 128);
    const float4* h04 = (const float4*)h0s;
    const float4* h14 = (const float4*)h1s;
#pragma unroll
    for (int k4 = 0; k4 < 32; ++k4) {
        float4 wv = wo4[k4];
        float4 a = h04[k4];
        float4 b = h14[k4];
        acc0 += wv.x * a.x + wv.y * a.y + wv.z * a.z + wv.w * a.w;
        acc1 += wv.x * b.x + wv.y * b.y + wv.z * b.z + wv.w * b.w;
    }
    out[b0 * 128 + t] = acc0;
    out[(b0 + 1) * 128 + t] = acc1;
}

// ---------------------------------------------------------------------------

extern "C" void kernel_launch(void* const* d_in, const int* in_sizes, int n_in,
                              void* d_out, int out_size)
{
    const float* x   = (const float*)d_in[0];
    const float* Wih = (const float*)d_in[1];
    const float* Whh = (const float*)d_in[2];
    const float* bih = (const float*)d_in[3];
    const float* bhh = (const float*)d_in[4];
    const float* Wo  = (const float*)d_in[5];
    const float* bo  = (const float*)d_in[6];
    float* out = (float*)d_out;

    // smem: A = 96 KB; B = (2*KS*WROW + 256)*4 = 199168 B
    cudaFuncSetAttribute(xg_gemm, cudaFuncAttributeMaxDynamicSharedMemorySize, 98304);
    cudaFuncSetAttribute(lstm_rec, cudaFuncAttributeMaxDynamicSharedMemorySize, 199168);

    xg_gemm<<<dim3(8192, 4), 256, 98304>>>(x, Wih, bih, bhh);
    lstm_rec<<<128, 128, 199168>>>(Whh, Wo, bo, out);
}

// round 3
// speedup vs baseline: 1.5131x; 1.1125x over previous
#include <cuda_runtime.h>
#include <math.h>

#define T_SEQ 2048
#define BATCH 256
// Kernel B k-split: per k-half (64 k's), SKS from smem, RKS from registers
#define SKS 28
#define RKS 36

typedef unsigned long long u64;

// xg scratch: [B][T][4H] fp32 = 1 GiB. __device__ global (no cudaMalloc allowed).
__device__ float g_xg[268435456];

// ---- f32x2 packed-math helpers (sm_103a FFMA2) --------------------------
__device__ __forceinline__ u64 pack2(float lo, float hi) {
    u64 r; asm("mov.b64 %0, {%1, %2};" : "=l"(r) : "f"(lo), "f"(hi)); return r;
}
__device__ __forceinline__ u64 dup2(float v) {
    u64 r; asm("mov.b64 %0, {%1, %1};" : "=l"(r) : "f"(v)); return r;
}
__device__ __forceinline__ void ffma2(u64& d, u64 a, u64 b) {
    asm("fma.rn.f32x2 %0, %1, %2, %0;" : "+l"(d) : "l"(a), "l"(b));
}
__device__ __forceinline__ u64 add2(u64 a, u64 b) {
    u64 r; asm("add.rn.f32x2 %0, %1, %2;" : "=l"(r) : "l"(a), "l"(b)); return r;
}
__device__ __forceinline__ void unpack2(u64 v, float& lo, float& hi) {
    asm("mov.b64 {%0, %1}, %2;" : "=f"(lo), "=f"(hi) : "l"(v));
}

__device__ __forceinline__ float sigf(float x) {
    return __fdividef(1.f, 1.f + __expf(-x));
}
// overflow-safe tanh: exp argument always <= 0
__device__ __forceinline__ float tanhx(float x) {
    float a = fabsf(x);
    float e = __expf(-2.f * a);
    float r = __fdividef(1.f - e, 1.f + e);
    return copysignf(r, x);
}

// ---------------------------------------------------------------------------
// Kernel A: xg[b,t,g] = sum_d x[b,t,d] * Wih[g,d] + bih[g] + bhh[g]
// (unchanged from R2: FFMA2 column-pair accumulation, ~fp32x2 roofline)
// ---------------------------------------------------------------------------
__global__ void __launch_bounds__(256, 2)
xg_gemm(const float* __restrict__ x, const float* __restrict__ Wih,
        const float* __restrict__ bih, const float* __restrict__ bhh)
{
    extern __shared__ float sm[];
    float* As = sm;            // [64][128]
    float* B0 = sm + 8192;     // [128][64] cols g0+0..63
    float* B1 = B0 + 8192;     // [128][64] cols g0+64..127

    const int tid = threadIdx.x;
    const int tx = tid & 31;
    const int ty = tid >> 5;
    const long row0 = (long)blockIdx.x * 64;
    const int g0 = blockIdx.y * 128;

    {
        const float4* x4 = (const float4*)x + row0 * 32;
        float4* As4 = (float4*)As;
#pragma unroll
        for (int i = 0; i < 8; ++i) As4[i * 256 + tid] = x4[i * 256 + tid];
    }
    {
        const float4* w4 = (const float4*)Wih + (long)g0 * 32;
#pragma unroll
        for (int i = 0; i < 16; ++i) {
            int idx = i * 256 + tid;
            int q  = idx >> 7;
            int gl = idx & 127;
            float4 w = w4[(long)gl * 32 + q];
            float* dst = (gl < 64 ? B0 : B1) + (gl & 63);
            int k = q * 4;
            dst[(k + 0) * 64] = w.x;
            dst[(k + 1) * 64] = w.y;
            dst[(k + 2) * 64] = w.z;
            dst[(k + 3) * 64] = w.w;
        }
    }
    __syncthreads();

    u64 acc0[8], acc1[8];
#pragma unroll
    for (int i = 0; i < 8; ++i) { acc0[i] = 0ull; acc1[i] = 0ull; }

    const float4* As4 = (const float4*)As;

#pragma unroll 2
    for (int k4 = 0; k4 < 32; ++k4) {
        float4 a[8];
#pragma unroll
        for (int i = 0; i < 8; ++i) a[i] = As4[(ty * 8 + i) * 32 + k4];
#pragma unroll
        for (int c = 0; c < 4; ++c) {
            int k = 4 * k4 + c;
            u64 b0 = *(const u64*)(B0 + k * 64 + 2 * tx);
            u64 b1 = *(const u64*)(B1 + k * 64 + 2 * tx);
#pragma unroll
            for (int i = 0; i < 8; ++i) {
                float av = (c == 0) ? a[i].x : (c == 1) ? a[i].y
                          : (c == 2) ? a[i].z : a[i].w;
                u64 ad = dup2(av);
                ffma2(acc0[i], ad, b0);
                ffma2(acc1[i], ad, b1);
            }
        }
    }

    int c00 = g0 + 2 * tx, c10 = g0 + 64 + 2 * tx;
    float2 bv0 = make_float2(bih[c00] + bhh[c00], bih[c00 + 1] + bhh[c00 + 1]);
    float2 bv1 = make_float2(bih[c10] + bhh[c10], bih[c10 + 1] + bhh[c10 + 1]);

#pragma unroll
    for (int i = 0; i < 8; ++i) {
        long r = row0 + ty * 8 + i;
        float lo, hi;
        unpack2(acc0[i], lo, hi);
        *(float2*)&g_xg[r * 512 + c00] = make_float2(lo + bv0.x, hi + bv0.y);
        unpack2(acc1[i], lo, hi);
        *(float2*)&g_xg[r * 512 + c10] = make_float2(lo + bv1.x, hi + bv1.y);
    }
}

// ---------------------------------------------------------------------------
// Kernel B: LSTM recurrence. 128 CTAs x 2 batch rows, 256 threads/CTA.
// Thread (j, kh): j = th & 127 (hidden index), kh = th >> 7 (k-half).
// Each thread accumulates gate-pair partials for BOTH rows over its 64 k's:
// SKS=28 k's from smem, RKS=36 k's from registers (144 weight regs).
// Partial sums exchanged via smem; thread (j,kh) finalizes row kh (owns c).
// 2 warps/SMSP for latency hiding; h in ping-pong smem buffers.
// ---------------------------------------------------------------------------
__global__ void __launch_bounds__(256, 1)
lstm_rec(const float* __restrict__ Whh, const float* __restrict__ Wo,
         const float* __restrict__ bo, float* __restrict__ out)
{
    extern __shared__ float sm[];
    float* WIF = sm;                        // [2*SKS][256] pairs (wi,wf)
    float* WGO = WIF + 2 * SKS * 256;       // [2*SKS][256] pairs (wg,wo)
    float* hbuf = WGO + 2 * SKS * 256;      // [2][256] ping-pong: row0 | row1
    u64*  part = (u64*)(hbuf + 512);        // [2][128][2] partial (aif,ago)

    const int th = threadIdx.x;
    const int j  = th & 127;
    const int kh = th >> 7;                 // my k-half & my row
    const int b0 = blockIdx.x * 2;

    // ---- smem weights: k in [0,SKS) and [64, 64+SKS), rows kr = half*SKS+q
    for (int e = th; e < 14 * 128; e += 256) {
        int q14 = e >> 7, jj = e & 127;
        int half = (q14 >= 7);
        int qq = q14 - 7 * half;
        int k = 64 * half + 4 * qq;
        int kr = half * SKS + 4 * qq;
        float4 vi = *(const float4*)&Whh[(0 * 128 + jj) * 128 + k];
        float4 vf = *(const float4*)&Whh[(1 * 128 + jj) * 128 + k];
        float4 vg = *(const float4*)&Whh[(2 * 128 + jj) * 128 + k];
        float4 vo = *(const float4*)&Whh[(3 * 128 + jj) * 128 + k];
        *(float2*)&WIF[(kr + 0) * 256 + 2 * jj] = make_float2(vi.x, vf.x);
        *(float2*)&WIF[(kr + 1) * 256 + 2 * jj] = make_float2(vi.y, vf.y);
        *(float2*)&WIF[(kr + 2) * 256 + 2 * jj] = make_float2(vi.z, vf.z);
        *(float2*)&WIF[(kr + 3) * 256 + 2 * jj] = make_float2(vi.w, vf.w);
        *(float2*)&WGO[(kr + 0) * 256 + 2 * jj] = make_float2(vg.x, vo.x);
        *(float2*)&WGO[(kr + 1) * 256 + 2 * jj] = make_float2(vg.y, vo.y);
        *(float2*)&WGO[(kr + 2) * 256 + 2 * jj] = make_float2(vg.z, vo.z);
        *(float2*)&WGO[(kr + 3) * 256 + 2 * jj] = make_float2(vg.w, vo.w);
    }
    // ---- register weights: k in [64*kh + SKS, 64*kh + 64)
    u64 wifr[RKS], wgor[RKS];
#pragma unroll
    for (int r = 0; r < RKS; ++r) {
        int k = 64 * kh + SKS + r;
        wifr[r] = pack2(Whh[(0 * 128 + j) * 128 + k], Whh[(1 * 128 + j) * 128 + k]);
        wgor[r] = pack2(Whh[(2 * 128 + j) * 128 + k], Whh[(3 * 128 + j) * 128 + k]);
    }

    hbuf[th] = 0.f; hbuf[256 + th] = 0.f;
    float c = 0.f;                          // cell state of my row

    const float* xgp = g_xg + (long)(b0 + kh) * T_SEQ * 512;
    float p0 = __ldg(xgp + j),       p1 = __ldg(xgp + 128 + j),
          p2 = __ldg(xgp + 256 + j), p3 = __ldg(xgp + 384 + j);

    __syncthreads();

    for (int step = 0; step < T_SEQ; ++step) {
        const float* hc = hbuf + ((step & 1) << 8);
        float* hn = hbuf + (((step + 1) & 1) << 8);

        // h over my k-half for BOTH rows (broadcast float4 loads)
        const float4* hA4 = (const float4*)(hc + 64 * kh);        // row 0
        const float4* hB4 = (const float4*)(hc + 128 + 64 * kh);  // row 1

        u64 aif0 = 0ull, ago0 = 0ull, aif1 = 0ull, ago1 = 0ull;

        // smem k's: 7 float4 chunks (28 k)
#pragma unroll
        for (int q = 0; q < 7; ++q) {
            float4 H0 = hA4[q], H1 = hB4[q];
            const float* pif = WIF + (kh * SKS + q * 4) * 256 + 2 * j;
            const float* pgo = WGO + (kh * SKS + q * 4) * 256 + 2 * j;
#pragma unroll
            for (int cc = 0; cc < 4; ++cc) {
                u64 wif = *(const u64*)(pif + cc * 256);
                u64 wgo = *(const u64*)(pgo + cc * 256);
                float hx0 = (cc == 0) ? H0.x : (cc == 1) ? H0.y : (cc == 2) ? H0.z : H0.w;
                float hx1 = (cc == 0) ? H1.x : (cc == 1) ? H1.y : (cc == 2) ? H1.z : H1.w;
                u64 d0 = dup2(hx0), d1 = dup2(hx1);
                ffma2(aif0, wif, d0); ffma2(ago0, wgo, d0);
                ffma2(aif1, wif, d1); ffma2(ago1, wgo, d1);
            }
        }
        // register k's: 9 float4 chunks (36 k)
#pragma unroll
        for (int q = 0; q < 9; ++q) {
            float4 H0 = hA4[7 + q], H1 = hB4[7 + q];
#pragma unroll
            for (int cc = 0; cc < 4; ++cc) {
                int r = q * 4 + cc;
                float hx0 = (cc == 0) ? H0.x : (cc == 1) ? H0.y : (cc == 2) ? H0.z : H0.w;
                float hx1 = (cc == 0) ? H1.x : (cc == 1) ? H1.y : (cc == 2) ? H1.z : H1.w;
                u64 d0 = dup2(hx0), d1 = dup2(hx1);
                ffma2(aif0, wifr[r], d0); ffma2(ago0, wgor[r], d0);
                ffma2(aif1, wifr[r], d1); ffma2(ago1, wgor[r], d1);
            }
        }

        // exchange: write partials of the OTHER row, keep my row's
        u64 myAif = kh ? aif1 : aif0;
        u64 myAgo = kh ? ago1 : ago0;
        part[(kh << 8) + 2 * j]     = kh ? aif0 : aif1;
        part[(kh << 8) + 2 * j + 1] = kh ? ago0 : ago1;
        __syncthreads();
        u64 aif = add2(add2(myAif, part[((1 - kh) << 8) + 2 * j]), pack2(p0, p1));
        u64 ago = add2(add2(myAgo, part[((1 - kh) << 8) + 2 * j + 1]), pack2(p2, p3));

        // prefetch next step's xg for my row (latency hidden by activations)
        {
            int ns = (step + 1 < T_SEQ) ? step + 1 : step;
            const float* qp = xgp + (long)ns * 512 + j;
            p0 = __ldg(qp); p1 = __ldg(qp + 128); p2 = __ldg(qp + 256); p3 = __ldg(qp + 384);
        }

        float ai, af, ag, ao;
        unpack2(aif, ai, af); unpack2(ago, ag, ao);
        float iv = sigf(ai), fv = sigf(af), gv = tanhx(ag), ov = sigf(ao);
        c = fv * c + iv * gv;
        float nh = ov * tanhx(c);
        hn[(kh << 7) + j] = nh;
        __syncthreads();
    }

    // Output projection: out[b, o] = h_last[b,:] . Wo[o,:] + bo[o]
    // Final h is in buffer 0 (T_SEQ even): row0 at hbuf[0..127], row1 at +128.
    if (th < 128) {
        int t = th;
        float acc0 = bo[t], acc1 = acc0;
        const float4* wo4 = (const float4*)(Wo + t * 128);
        const float4* h04 = (const float4*)hbuf;
        const float4* h14 = (const float4*)(hbuf + 128);
#pragma unroll
        for (int k4 = 0; k4 < 32; ++k4) {
            float4 wv = wo4[k4];
            float4 a = h04[k4];
            float4 b = h14[k4];
            acc0 += wv.x * a.x + wv.y * a.y + wv.z * a.z + wv.w * a.w;
            acc1 += wv.x * b.x + wv.y * b.y + wv.z * b.z + wv.w * b.w;
        }
        out[b0 * 128 + t] = acc0;
        out[(b0 + 1) * 128 + t] = acc1;
    }
}

// ---------------------------------------------------------------------------

extern "C" void kernel_launch(void* const* d_in, const int* in_sizes, int n_in,
                              void* d_out, int out_size)
{
    const float* x   = (const float*)d_in[0];
    const float* Wih = (const float*)d_in[1];
    const float* Whh = (const float*)d_in[2];
    const float* bih = (const float*)d_in[3];
    const float* bhh = (const float*)d_in[4];
    const float* Wo  = (const float*)d_in[5];
    const float* bo  = (const float*)d_in[6];
    float* out = (float*)d_out;

    // lstm_rec smem: weights 2*(2*SKS*256)*4 = 114688 B, h 2048 B, part 4096 B
    const int smB = 2 * (2 * SKS * 256) * 4 + 2048 + 4096;
    cudaFuncSetAttribute(xg_gemm, cudaFuncAttributeMaxDynamicSharedMemorySize, 98304);
    cudaFuncSetAttribute(lstm_rec, cudaFuncAttributeMaxDynamicSharedMemorySize, smB);

    xg_gemm<<<dim3(8192, 4), 256, 98304>>>(x, Wih, bih, bhh);
    lstm_rec<<<128, 256, smB>>>(Whh, Wo, bo, out);
}

// round 4
// speedup vs baseline: 1.5505x; 1.0247x over previous
#include <cuda_runtime.h>
#include <math.h>

#define T_SEQ 2048
#define BATCH 256
// Kernel B per k-quarter (32 k): RKQ in registers, SKQ in smem
#define RKQ 20
#define SKQ 12

typedef unsigned long long u64;

// xg scratch: [B][T][4H] fp32 = 1 GiB. __device__ global (no cudaMalloc allowed).
__device__ float g_xg[268435456];

// ---- f32x2 packed-math helpers (sm_103a FFMA2) --------------------------
__device__ __forceinline__ u64 pack2(float lo, float hi) {
    u64 r; asm("mov.b64 %0, {%1, %2};" : "=l"(r) : "f"(lo), "f"(hi)); return r;
}
__device__ __forceinline__ u64 dup2(float v) {
    u64 r; asm("mov.b64 %0, {%1, %1};" : "=l"(r) : "f"(v)); return r;
}
__device__ __forceinline__ void ffma2(u64& d, u64 a, u64 b) {
    asm("fma.rn.f32x2 %0, %1, %2, %0;" : "+l"(d) : "l"(a), "l"(b));
}
__device__ __forceinline__ u64 add2(u64 a, u64 b) {
    u64 r; asm("add.rn.f32x2 %0, %1, %2;" : "=l"(r) : "l"(a), "l"(b)); return r;
}
__device__ __forceinline__ void unpack2(u64 v, float& lo, float& hi) {
    asm("mov.b64 {%0, %1}, %2;" : "=f"(lo), "=f"(hi) : "l"(v));
}

__device__ __forceinline__ float sigf(float x) {
    return __fdividef(1.f, 1.f + __expf(-x));
}
// overflow-safe tanh: exp argument always <= 0
__device__ __forceinline__ float tanhx(float x) {
    float a = fabsf(x);
    float e = __expf(-2.f * a);
    float r = __fdividef(1.f - e, 1.f + e);
    return copysignf(r, x);
}

// ---------------------------------------------------------------------------
// Kernel A: xg = x @ Wih^T + bih + bhh  (unchanged; ~95% of fp32x2 roofline)
// ---------------------------------------------------------------------------
__global__ void __launch_bounds__(256, 2)
xg_gemm(const float* __restrict__ x, const float* __restrict__ Wih,
        const float* __restrict__ bih, const float* __restrict__ bhh)
{
    extern __shared__ float sm[];
    float* As = sm;
    float* B0 = sm + 8192;
    float* B1 = B0 + 8192;

    const int tid = threadIdx.x;
    const int tx = tid & 31;
    const int ty = tid >> 5;
    const long row0 = (long)blockIdx.x * 64;
    const int g0 = blockIdx.y * 128;

    {
        const float4* x4 = (const float4*)x + row0 * 32;
        float4* As4 = (float4*)As;
#pragma unroll
        for (int i = 0; i < 8; ++i) As4[i * 256 + tid] = x4[i * 256 + tid];
    }
    {
        const float4* w4 = (const float4*)Wih + (long)g0 * 32;
#pragma unroll
        for (int i = 0; i < 16; ++i) {
            int idx = i * 256 + tid;
            int q  = idx >> 7;
            int gl = idx & 127;
            float4 w = w4[(long)gl * 32 + q];
            float* dst = (gl < 64 ? B0 : B1) + (gl & 63);
            int k = q * 4;
            dst[(k + 0) * 64] = w.x;
            dst[(k + 1) * 64] = w.y;
            dst[(k + 2) * 64] = w.z;
            dst[(k + 3) * 64] = w.w;
        }
    }
    __syncthreads();

    u64 acc0[8], acc1[8];
#pragma unroll
    for (int i = 0; i < 8; ++i) { acc0[i] = 0ull; acc1[i] = 0ull; }

    const float4* As4 = (const float4*)As;

#pragma unroll 2
    for (int k4 = 0; k4 < 32; ++k4) {
        float4 a[8];
#pragma unroll
        for (int i = 0; i < 8; ++i) a[i] = As4[(ty * 8 + i) * 32 + k4];
#pragma unroll
        for (int c = 0; c < 4; ++c) {
            int k = 4 * k4 + c;
            u64 b0 = *(const u64*)(B0 + k * 64 + 2 * tx);
            u64 b1 = *(const u64*)(B1 + k * 64 + 2 * tx);
#pragma unroll
            for (int i = 0; i < 8; ++i) {
                float av = (c == 0) ? a[i].x : (c == 1) ? a[i].y
                          : (c == 2) ? a[i].z : a[i].w;
                u64 ad = dup2(av);
                ffma2(acc0[i], ad, b0);
                ffma2(acc1[i], ad, b1);
            }
        }
    }

    int c00 = g0 + 2 * tx, c10 = g0 + 64 + 2 * tx;
    float2 bv0 = make_float2(bih[c00] + bhh[c00], bih[c00 + 1] + bhh[c00 + 1]);
    float2 bv1 = make_float2(bih[c10] + bhh[c10], bih[c10 + 1] + bhh[c10 + 1]);

#pragma unroll
    for (int i = 0; i < 8; ++i) {
        long r = row0 + ty * 8 + i;
        float lo, hi;
        unpack2(acc0[i], lo, hi);
        *(float2*)&g_xg[r * 512 + c00] = make_float2(lo + bv0.x, hi + bv0.y);
        unpack2(acc1[i], lo, hi);
        *(float2*)&g_xg[r * 512 + c10] = make_float2(lo + bv1.x, hi + bv1.y);
    }
}

// ---------------------------------------------------------------------------
// Kernel B: LSTM recurrence. 128 CTAs x 2 rows, 512 threads/CTA.
// Thread (j, kq): j = th & 127, kq = th >> 7 owns 32 k's (k-quarter).
// Per thread: RKQ=20 k from registers (80 regs), SKQ=12 k from smem; partials
// for BOTH rows, gate-pair FFMA2. Reduction across 4 kq via smem ulonglong2;
// threads kq<2 finalize row=kq (activations + h write). 4 warps/SMSP.
// ---------------------------------------------------------------------------
__global__ void __launch_bounds__(512, 1)
lstm_rec(const float* __restrict__ Whh, const float* __restrict__ Wo,
         const float* __restrict__ bo, float* __restrict__ out)
{
    extern __shared__ float sm[];
    float* WIF = sm;                         // [48][256] pairs (wi,wf)
    float* WGO = WIF + 48 * 256;             // [48][256] pairs (wg,wo)
    float* hbuf = WGO + 48 * 256;            // [2][256] ping-pong (row*128+j)
    ulonglong2* part = (ulonglong2*)(hbuf + 512);  // [2][4][128] (aif,ago)

    const int th = threadIdx.x;
    const int j  = th & 127;
    const int kq = th >> 7;                  // k-quarter; also my row if kq<2
    const int b0 = blockIdx.x * 2;
    const int k0 = 32 * kq;

    // ---- smem weights: for each kq, k in [32kq+RKQ, 32kq+32) -> ks = kq*SKQ+..
    for (int e = th; e < 48 * 128; e += 512) {
        int jj = e & 127, ks = e >> 7;
        int q = ks / SKQ, kk = ks % SKQ;
        int k = 32 * q + RKQ + kk;
        float wi = Whh[(0 * 128 + jj) * 128 + k];
        float wf = Whh[(1 * 128 + jj) * 128 + k];
        float wg = Whh[(2 * 128 + jj) * 128 + k];
        float wo = Whh[(3 * 128 + jj) * 128 + k];
        *(float2*)&WIF[ks * 256 + 2 * jj] = make_float2(wi, wf);
        *(float2*)&WGO[ks * 256 + 2 * jj] = make_float2(wg, wo);
    }
    // ---- register weights: k in [32kq, 32kq+RKQ)
    u64 wifr[RKQ], wgor[RKQ];
#pragma unroll
    for (int r = 0; r < RKQ; ++r) {
        int k = k0 + r;
        wifr[r] = pack2(Whh[(0 * 128 + j) * 128 + k], Whh[(1 * 128 + j) * 128 + k]);
        wgor[r] = pack2(Whh[(2 * 128 + j) * 128 + k], Whh[(3 * 128 + j) * 128 + k]);
    }

    if (th < 512) { hbuf[th] = 0.f; }        // both ping-pong buffers zero
    float c = 0.f;                           // cell state (finalizers only use)

    const float* xgp = g_xg + (long)(b0 + (kq & 1)) * T_SEQ * 512;
    float p0 = 0.f, p1 = 0.f, p2 = 0.f, p3 = 0.f;
    if (kq < 2) {
        p0 = __ldg(xgp + j);       p1 = __ldg(xgp + 128 + j);
        p2 = __ldg(xgp + 256 + j); p3 = __ldg(xgp + 384 + j);
    }

    __syncthreads();

    for (int step = 0; step < T_SEQ; ++step) {
        const float* hc = hbuf + ((step & 1) << 8);
        float* hn = hbuf + (((step + 1) & 1) << 8);

        const float4* hA4 = (const float4*)(hc + k0);         // row 0, my k's
        const float4* hB4 = (const float4*)(hc + 128 + k0);   // row 1, my k's

        u64 aif0 = 0ull, ago0 = 0ull, aif1 = 0ull, ago1 = 0ull;

        // register k's: 5 float4 chunks (20 k)
#pragma unroll
        for (int q = 0; q < RKQ / 4; ++q) {
            float4 H0 = hA4[q], H1 = hB4[q];
#pragma unroll
            for (int cc = 0; cc < 4; ++cc) {
                int r = 4 * q + cc;
                float hx0 = (cc == 0) ? H0.x : (cc == 1) ? H0.y : (cc == 2) ? H0.z : H0.w;
                float hx1 = (cc == 0) ? H1.x : (cc == 1) ? H1.y : (cc == 2) ? H1.z : H1.w;
                u64 d0 = dup2(hx0), d1 = dup2(hx1);
                ffma2(aif0, wifr[r], d0); ffma2(ago0, wgor[r], d0);
                ffma2(aif1, wifr[r], d1); ffma2(ago1, wgor[r], d1);
            }
        }
        // smem k's: 3 float4 chunks (12 k)
#pragma unroll
        for (int q = 0; q < SKQ / 4; ++q) {
            float4 H0 = hA4[RKQ / 4 + q], H1 = hB4[RKQ / 4 + q];
            const float* pif = WIF + (kq * SKQ + 4 * q) * 256 + 2 * j;
            const float* pgo = WGO + (kq * SKQ + 4 * q) * 256 + 2 * j;
#pragma unroll
            for (int cc = 0; cc < 4; ++cc) {
                u64 wif = *(const u64*)(pif + cc * 256);
                u64 wgo = *(const u64*)(pgo + cc * 256);
                float hx0 = (cc == 0) ? H0.x : (cc == 1) ? H0.y : (cc == 2) ? H0.z : H0.w;
                float hx1 = (cc == 0) ? H1.x : (cc == 1) ? H1.y : (cc == 2) ? H1.z : H1.w;
                u64 d0 = dup2(hx0), d1 = dup2(hx1);
                ffma2(aif0, wif, d0); ffma2(ago0, wgo, d0);
                ffma2(aif1, wif, d1); ffma2(ago1, wgo, d1);
            }
        }

        // exchange partials: P(row,kq,j) index = (row<<9) + (kq<<7) + j
        if (kq == 0) {
            part[(1 << 9) + (0 << 7) + j] = make_ulonglong2(aif1, ago1);
        } else if (kq == 1) {
            part[(0 << 9) + (1 << 7) + j] = make_ulonglong2(aif0, ago0);
        } else {
            part[(0 << 9) + (kq << 7) + j] = make_ulonglong2(aif0, ago0);
            part[(1 << 9) + (kq << 7) + j] = make_ulonglong2(aif1, ago1);
        }
        __syncthreads();

        if (kq < 2) {
            // my row = kq; own partial kept in regs
            u64 aif = (kq == 0) ? aif0 : aif1;
            u64 ago = (kq == 0) ? ago0 : ago1;
#pragma unroll
            for (int qq = 1; qq < 4; ++qq) {
                int src = (kq + qq) & 3;      // the other three quarters
                ulonglong2 v = part[(kq << 9) + (src << 7) + j];
                aif = add2(aif, v.x);
                ago = add2(ago, v.y);
            }
            aif = add2(aif, pack2(p0, p1));
            ago = add2(ago, pack2(p2, p3));

            // prefetch next step's xg
            int ns = (step + 1 < T_SEQ) ? step + 1 : step;
            const float* qp = xgp + (long)ns * 512 + j;
            p0 = __ldg(qp); p1 = __ldg(qp + 128); p2 = __ldg(qp + 256); p3 = __ldg(qp + 384);

            float ai, af, ag, ao;
            unpack2(aif, ai, af); unpack2(ago, ag, ao);
            float iv = sigf(ai), fv = sigf(af), gv = tanhx(ag), ov = sigf(ao);
            c = fv * c + iv * gv;
            float nh = ov * tanhx(c);
            hn[(kq << 7) + j] = nh;
        }
        __syncthreads();
    }

    // Output projection (final h in buffer 0 since T_SEQ is even)
    if (th < 128) {
        int t = th;
        float acc0 = bo[t], acc1 = acc0;
        const float4* wo4 = (const float4*)(Wo + t * 128);
        const float4* h04 = (const float4*)hbuf;
        const float4* h14 = (const float4*)(hbuf + 128);
#pragma unroll
        for (int k4 = 0; k4 < 32; ++k4) {
            float4 wv = wo4[k4];
            float4 a = h04[k4];
            float4 b = h14[k4];
            acc0 += wv.x * a.x + wv.y * a.y + wv.z * a.z + wv.w * a.w;
            acc1 += wv.x * b.x + wv.y * b.y + wv.z * b.z + wv.w * b.w;
        }
        out[b0 * 128 + t] = acc0;
        out[(b0 + 1) * 128 + t] = acc1;
    }
}

// ---------------------------------------------------------------------------

extern "C" void kernel_launch(void* const* d_in, const int* in_sizes, int n_in,
                              void* d_out, int out_size)
{
    const float* x   = (const float*)d_in[0];
    const float* Wih = (const float*)d_in[1];
    const float* Whh = (const float*)d_in[2];
    const float* bih = (const float*)d_in[3];
    const float* bhh = (const float*)d_in[4];
    const float* Wo  = (const float*)d_in[5];
    const float* bo  = (const float*)d_in[6];
    float* out = (float*)d_out;

    // lstm_rec smem: WIF+WGO 2*48*256*4 = 98304, h 2048, part 16384 -> 116736
    const int smB = 98304 + 2048 + 16384;
    cudaFuncSetAttribute(xg_gemm, cudaFuncAttributeMaxDynamicSharedMemorySize, 98304);
    cudaFuncSetAttribute(lstm_rec, cudaFuncAttributeMaxDynamicSharedMemorySize, smB);

    xg_gemm<<<dim3(8192, 4), 256, 98304>>>(x, Wih, bih, bhh);
    lstm_rec<<<128, 512, smB>>>(Whh, Wo, bo, out);
}